// round 10
// baseline (speedup 1.0000x reference)
#include <cuda_runtime.h>
#include <math.h>

#define BATCH 128
#define HDIM 512
#define WDIM 512
#define HW (HDIM*WDIM)          // 262144
#define SPLIT 8
#define NBLK (BATCH*SPLIT)      // 1024 blocks
#define CHUNK (HW/SPLIT)        // 32768 elements
#define NT 512
#define NV (CHUNK/4/NT)         // 16 float4 per thread
#define NEGINF (-3.402823466e+38f)

// Scratch (device globals; no allocations allowed)
__device__ float g_psum[NBLK];
__device__ float g_fk [NBLK]; __device__ int g_fi [NBLK];
__device__ float g_b1u[NBLK]; __device__ int g_b1i[NBLK]; __device__ float g_b1c[NBLK];
__device__ float g_b2u[NBLK]; __device__ int g_b2i[NBLK]; __device__ float g_b2c[NBLK];
__device__ unsigned int g_ctr;   // zero-init; last block resets each launch

__device__ __forceinline__ bool better(float s, int i, float s2, int i2) {
    return s > s2 || (s == s2 && i < i2);
}

// -ln(u): poly in t=1-u where argmax contenders live (rel err < 1e-8 for
// t < 1/16), MUFU lg2 elsewhere (non-contenders; their error is harmless).
__device__ __forceinline__ float neg_ln(float u) {
    u = fmaxf(u, 1e-12f);            // reference clip (upper clip no-op in fp32)
    float t = 1.0f - u;
    float wp = t*(1.0f + t*(0.5f + t*(0.33333334f + t*(0.25f +
               t*(0.2f + t*(0.16666667f + t*0.14285715f))))));
    float wm = __log2f(u) * -0.69314718f;
    return (t < 0.0625f) ? wp : wm;
}

__global__ void __launch_bounds__(NT, 2)
k_all(const float* __restrict__ x, const float* __restrict__ ufg,
      const float* __restrict__ ubg, float* __restrict__ out) {
    int blk = blockIdx.x;
    int b = blk / SPLIT, ch = blk % SPLIT;
    size_t off = (size_t)b*HW + (size_t)ch*CHUNK;
    const float4* cam = reinterpret_cast<const float4*>(x + off);
    const float4* uf  = reinterpret_cast<const float4*>(ufg + off);
    const float4* ub  = reinterpret_cast<const float4*>(ubg + off);
    float4* op = reinterpret_cast<float4*>(out + off);
    int t = threadIdx.x;

    float sum = 0.f;
    float fk = NEGINF; int fi = 0;
    float bu = -1.f;   int bi = 0; float bc = 0.f;
    const float4 fill = make_float4(-255.f, -255.f, -255.f, -255.f);

    // software pipeline: prefetch next iteration's 3 float4s while computing
    float4 c = cam[t];
    float4 f = uf[t];
    float4 g = ub[t];

    #pragma unroll 8
    for (int it = 0; it < NV; ++it) {
        float4 cn, fn, gn;
        if (it + 1 < NV) {
            int vn = (it+1)*NT + t;
            cn = cam[vn]; fn = uf[vn]; gn = ub[vn];
        }
        op[it*NT + t] = fill;
        int base = ch*CHUNK + (it*NT + t)*4;
        float cc[4] = {c.x, c.y, c.z, c.w};
        float ff[4] = {f.x, f.y, f.z, f.w};
        float gg[4] = {g.x, g.y, g.z, g.w};
        #pragma unroll
        for (int j = 0; j < 4; ++j) {
            float ce = cc[j] + 1e-6f;
            sum += ce;
            float key = __fdividef(ce, neg_ln(ff[j]));   // fg rank key
            if (key > fk) { fk = key; fi = base + j; }   // ascending idx -> strict >
            float u = gg[j];
            if (u > bu) { bu = u; bi = base + j; bc = cc[j]; }
        }
        if (it + 1 < NV) { c = cn; f = fn; g = gn; }
    }

    __shared__ float s_sum[NT];
    __shared__ float s_fk[NT];  __shared__ int s_fi[NT];
    __shared__ float s_b1u[NT]; __shared__ int s_b1i[NT]; __shared__ float s_b1c[NT];
    __shared__ float s_b2u[NT]; __shared__ int s_b2i[NT]; __shared__ float s_b2c[NT];
    s_sum[t] = sum;
    s_fk[t] = fk;  s_fi[t] = fi;
    s_b1u[t] = bu; s_b1i[t] = bi; s_b1c[t] = bc;
    s_b2u[t] = -1.f; s_b2i[t] = 0x7FFFFFFF; s_b2c[t] = 0.f;
    __syncthreads();

    for (int o = NT/2; o > 0; o >>= 1) {
        if (t < o) {
            s_sum[t] += s_sum[t + o];
            if (better(s_fk[t+o], s_fi[t+o], s_fk[t], s_fi[t])) {
                s_fk[t] = s_fk[t+o]; s_fi[t] = s_fi[t+o];
            }
            float a1 = s_b1u[t],   b1 = s_b1u[t+o];
            int   a1i = s_b1i[t],  b1i = s_b1i[t+o];
            float a1c = s_b1c[t],  b1c = s_b1c[t+o];
            float a2 = s_b2u[t],   b2 = s_b2u[t+o];
            int   a2i = s_b2i[t],  b2i = s_b2i[t+o];
            float a2c = s_b2c[t],  b2c = s_b2c[t+o];
            if (better(b1, b1i, a1, a1i)) {
                s_b1u[t] = b1; s_b1i[t] = b1i; s_b1c[t] = b1c;
                if (better(a1, a1i, b2, b2i)) { s_b2u[t] = a1; s_b2i[t] = a1i; s_b2c[t] = a1c; }
                else                          { s_b2u[t] = b2; s_b2i[t] = b2i; s_b2c[t] = b2c; }
            } else {
                if (better(b1, b1i, a2, a2i)) { s_b2u[t] = b1; s_b2i[t] = b1i; s_b2c[t] = b1c; }
            }
        }
        __syncthreads();
    }
    __shared__ bool is_last;
    if (t == 0) {
        g_psum[blk] = s_sum[0];
        g_fk[blk] = s_fk[0];   g_fi[blk] = s_fi[0];
        g_b1u[blk] = s_b1u[0]; g_b1i[blk] = s_b1i[0]; g_b1c[blk] = s_b1c[0];
        g_b2u[blk] = s_b2u[0]; g_b2i[blk] = s_b2i[0]; g_b2c[blk] = s_b2c[0];
        __threadfence();                           // publish partials + fill stores
        unsigned int v = atomicAdd(&g_ctr, 1u);
        is_last = (v == (unsigned)(NBLK - 1));
    }
    __syncthreads();
    if (!is_last) return;

    // ---- last block: finalize all batches (one thread per batch) ----
    if (t == 0) g_ctr = 0;                         // reset for next graph replay
    if (t >= BATCH) return;
    int bb = t;

    float S = 0.f;
    #pragma unroll
    for (int c2 = 0; c2 < SPLIT; ++c2) S += g_psum[bb*SPLIT + c2];
    float invS = 1.0f / S;

    float ffk = NEGINF; int ffi = 0;
    #pragma unroll
    for (int c2 = 0; c2 < SPLIT; ++c2) {
        float s = g_fk[bb*SPLIT + c2]; int i = g_fi[bb*SPLIT + c2];
        if (better(s, i, ffk, ffi)) { ffk = s; ffi = i; }
    }

    // bg: exact reference scoring of the 16 candidates
    float bsc = NEGINF; int bbi = 0;
    #pragma unroll
    for (int c2 = 0; c2 < SPLIT; ++c2) {
        int k = bb*SPLIT + c2;
        #pragma unroll
        for (int w = 0; w < 2; ++w) {
            float u   = w ? g_b2u[k] : g_b1u[k];
            int   idx = w ? g_b2i[k] : g_b1i[k];
            float cm  = w ? g_b2c[k] : g_b1c[k];
            float uc = fmaxf(u, 1e-12f);
            float gmb = -logf(-logf(uc));
            float p = (cm + 1e-6f) * invS;
            float s = log1pf(-p) + gmb;
            if (better(s, idx, bsc, bbi)) { bsc = s; bbi = idx; }
        }
    }

    int fr = ffi >> 9, fc = ffi & 511;
    int br = bbi >> 9, bc2 = bbi & 511;
    float* o = out + (size_t)bb*HW;
    #pragma unroll
    for (int dr = -1; dr <= 1; ++dr) {
        #pragma unroll
        for (int dc = -1; dc <= 1; ++dc) {
            int r = fr + dr, c2 = fc + dc;
            if (r >= 0 && r < HDIM && c2 >= 0 && c2 < WDIM &&
                !(abs(r - br) <= 1 && abs(c2 - bc2) <= 1))
                o[r*WDIM + c2] = 1.0f;
            r = br + dr; c2 = bc2 + dc;
            if (r >= 0 && r < HDIM && c2 >= 0 && c2 < WDIM &&
                !(abs(r - fr) <= 1 && abs(c2 - fc) <= 1))
                o[r*WDIM + c2] = 0.0f;
        }
    }
}

extern "C" void kernel_launch(void* const* d_in, const int* in_sizes, int n_in,
                              void* d_out, int out_size) {
    const float* x   = (const float*)d_in[0];
    const float* ufg = (const float*)d_in[1];
    const float* ubg = (const float*)d_in[2];
    float* out = (float*)d_out;
    k_all<<<NBLK, NT>>>(x, ufg, ubg, out);
}

// round 11
// speedup vs baseline: 1.1207x; 1.1207x over previous
#include <cuda_runtime.h>
#include <math.h>

#define BATCH 128
#define HDIM 512
#define WDIM 512
#define HW (HDIM*WDIM)          // 262144
#define SPLIT 2
#define NBLK (BATCH*SPLIT)      // 256 blocks
#define CHUNK (HW/SPLIT)        // 131072 elements
#define NT 512
#define NV (CHUNK/4/NT)         // 64 float4 per thread
#define NEGINF (-3.402823466e+38f)

// Scratch (device globals; no allocations allowed)
__device__ float g_psum[NBLK];
__device__ float g_fk [NBLK]; __device__ int g_fi [NBLK];
__device__ float g_b1u[NBLK]; __device__ int g_b1i[NBLK]; __device__ float g_b1c[NBLK];
__device__ float g_b2u[NBLK]; __device__ int g_b2i[NBLK]; __device__ float g_b2c[NBLK];
__device__ unsigned int g_ctr;   // zero-init; last block resets each launch

__device__ __forceinline__ bool better(float s, int i, float s2, int i2) {
    return s > s2 || (s == s2 && i < i2);
}

// -ln(u): poly in t=1-u where argmax contenders live (rel err < 1e-8 for
// t < 1/16), MUFU lg2 elsewhere (non-contenders; their error is harmless).
__device__ __forceinline__ float neg_ln(float u) {
    u = fmaxf(u, 1e-12f);            // reference clip (upper clip no-op in fp32)
    float t = 1.0f - u;
    float wp = t*(1.0f + t*(0.5f + t*(0.33333334f + t*(0.25f +
               t*(0.2f + t*(0.16666667f + t*0.14285715f))))));
    float wm = __log2f(u) * -0.69314718f;
    return (t < 0.0625f) ? wp : wm;
}

__global__ void __launch_bounds__(NT, 2)
k_all(const float* __restrict__ x, const float* __restrict__ ufg,
      const float* __restrict__ ubg, float* __restrict__ out) {
    int blk = blockIdx.x;
    int b = blk / SPLIT, ch = blk % SPLIT;
    size_t off = (size_t)b*HW + (size_t)ch*CHUNK;
    const float4* cam = reinterpret_cast<const float4*>(x + off);
    const float4* uf  = reinterpret_cast<const float4*>(ufg + off);
    const float4* ub  = reinterpret_cast<const float4*>(ubg + off);
    float4* op = reinterpret_cast<float4*>(out + off);
    int t = threadIdx.x;

    float sum = 0.f;
    float fk = NEGINF; int fi = 0;
    float bu = -1.f;   int bi = 0; float bc = 0.f;
    const float4 fill = make_float4(-255.f, -255.f, -255.f, -255.f);

    // software pipeline: prefetch next iteration's 3 float4s while computing
    float4 c = cam[t];
    float4 f = uf[t];
    float4 g = ub[t];

    #pragma unroll 8
    for (int it = 0; it < NV; ++it) {
        float4 cn, fn, gn;
        if (it + 1 < NV) {
            int vn = (it+1)*NT + t;
            cn = cam[vn]; fn = uf[vn]; gn = ub[vn];
        }
        op[it*NT + t] = fill;
        int base = ch*CHUNK + (it*NT + t)*4;
        float cc[4] = {c.x, c.y, c.z, c.w};
        float ff[4] = {f.x, f.y, f.z, f.w};
        float gg[4] = {g.x, g.y, g.z, g.w};
        #pragma unroll
        for (int j = 0; j < 4; ++j) {
            float ce = cc[j] + 1e-6f;
            sum += ce;
            float key = __fdividef(ce, neg_ln(ff[j]));   // fg rank key
            if (key > fk) { fk = key; fi = base + j; }   // ascending idx -> strict >
            float u = gg[j];
            if (u > bu) { bu = u; bi = base + j; bc = cc[j]; }
        }
        if (it + 1 < NV) { c = cn; f = fn; g = gn; }
    }

    __shared__ float s_sum[NT];
    __shared__ float s_fk[NT];  __shared__ int s_fi[NT];
    __shared__ float s_b1u[NT]; __shared__ int s_b1i[NT]; __shared__ float s_b1c[NT];
    __shared__ float s_b2u[NT]; __shared__ int s_b2i[NT]; __shared__ float s_b2c[NT];
    s_sum[t] = sum;
    s_fk[t] = fk;  s_fi[t] = fi;
    s_b1u[t] = bu; s_b1i[t] = bi; s_b1c[t] = bc;
    s_b2u[t] = -1.f; s_b2i[t] = 0x7FFFFFFF; s_b2c[t] = 0.f;
    __syncthreads();

    for (int o = NT/2; o > 0; o >>= 1) {
        if (t < o) {
            s_sum[t] += s_sum[t + o];
            if (better(s_fk[t+o], s_fi[t+o], s_fk[t], s_fi[t])) {
                s_fk[t] = s_fk[t+o]; s_fi[t] = s_fi[t+o];
            }
            float a1 = s_b1u[t],   b1 = s_b1u[t+o];
            int   a1i = s_b1i[t],  b1i = s_b1i[t+o];
            float a1c = s_b1c[t],  b1c = s_b1c[t+o];
            float a2 = s_b2u[t],   b2 = s_b2u[t+o];
            int   a2i = s_b2i[t],  b2i = s_b2i[t+o];
            float a2c = s_b2c[t],  b2c = s_b2c[t+o];
            if (better(b1, b1i, a1, a1i)) {
                s_b1u[t] = b1; s_b1i[t] = b1i; s_b1c[t] = b1c;
                if (better(a1, a1i, b2, b2i)) { s_b2u[t] = a1; s_b2i[t] = a1i; s_b2c[t] = a1c; }
                else                          { s_b2u[t] = b2; s_b2i[t] = b2i; s_b2c[t] = b2c; }
            } else {
                if (better(b1, b1i, a2, a2i)) { s_b2u[t] = b1; s_b2i[t] = b1i; s_b2c[t] = b1c; }
            }
        }
        __syncthreads();
    }
    __shared__ bool is_last;
    if (t == 0) {
        g_psum[blk] = s_sum[0];
        g_fk[blk] = s_fk[0];   g_fi[blk] = s_fi[0];
        g_b1u[blk] = s_b1u[0]; g_b1i[blk] = s_b1i[0]; g_b1c[blk] = s_b1c[0];
        g_b2u[blk] = s_b2u[0]; g_b2i[blk] = s_b2i[0]; g_b2c[blk] = s_b2c[0];
        __threadfence();                           // publish partials + fill stores
        unsigned int v = atomicAdd(&g_ctr, 1u);
        is_last = (v == (unsigned)(NBLK - 1));
    }
    __syncthreads();
    if (!is_last) return;

    // ---- last block: finalize all batches (one thread per batch) ----
    if (t == 0) g_ctr = 0;                         // reset for next graph replay
    if (t >= BATCH) return;
    int bb = t;

    float S = 0.f;
    #pragma unroll
    for (int c2 = 0; c2 < SPLIT; ++c2) S += g_psum[bb*SPLIT + c2];
    float invS = 1.0f / S;

    float ffk = NEGINF; int ffi = 0;
    #pragma unroll
    for (int c2 = 0; c2 < SPLIT; ++c2) {
        float s = g_fk[bb*SPLIT + c2]; int i = g_fi[bb*SPLIT + c2];
        if (better(s, i, ffk, ffi)) { ffk = s; ffi = i; }
    }

    // bg: exact reference scoring of the 4 candidates
    float bsc = NEGINF; int bbi = 0;
    #pragma unroll
    for (int c2 = 0; c2 < SPLIT; ++c2) {
        int k = bb*SPLIT + c2;
        #pragma unroll
        for (int w = 0; w < 2; ++w) {
            float u   = w ? g_b2u[k] : g_b1u[k];
            int   idx = w ? g_b2i[k] : g_b1i[k];
            float cm  = w ? g_b2c[k] : g_b1c[k];
            float uc = fmaxf(u, 1e-12f);
            float gmb = -logf(-logf(uc));
            float p = (cm + 1e-6f) * invS;
            float s = log1pf(-p) + gmb;
            if (better(s, idx, bsc, bbi)) { bsc = s; bbi = idx; }
        }
    }

    int fr = ffi >> 9, fc = ffi & 511;
    int br = bbi >> 9, bc2 = bbi & 511;
    float* o = out + (size_t)bb*HW;
    #pragma unroll
    for (int dr = -1; dr <= 1; ++dr) {
        #pragma unroll
        for (int dc = -1; dc <= 1; ++dc) {
            int r = fr + dr, c2 = fc + dc;
            if (r >= 0 && r < HDIM && c2 >= 0 && c2 < WDIM &&
                !(abs(r - br) <= 1 && abs(c2 - bc2) <= 1))
                o[r*WDIM + c2] = 1.0f;
            r = br + dr; c2 = bc2 + dc;
            if (r >= 0 && r < HDIM && c2 >= 0 && c2 < WDIM &&
                !(abs(r - fr) <= 1 && abs(c2 - fc) <= 1))
                o[r*WDIM + c2] = 0.0f;
        }
    }
}

extern "C" void kernel_launch(void* const* d_in, const int* in_sizes, int n_in,
                              void* d_out, int out_size) {
    const float* x   = (const float*)d_in[0];
    const float* ufg = (const float*)d_in[1];
    const float* ubg = (const float*)d_in[2];
    float* out = (float*)d_out;
    k_all<<<NBLK, NT>>>(x, ufg, ubg, out);
}

// round 12
// speedup vs baseline: 1.1256x; 1.0044x over previous
#include <cuda_runtime.h>
#include <math.h>

#define BATCH 128
#define HDIM 512
#define WDIM 512
#define HW (HDIM*WDIM)          // 262144
#define SPLIT 2
#define NBLK (BATCH*SPLIT)      // 256 blocks
#define CHUNK (HW/SPLIT)        // 131072 elements
#define NT 512
#define NV (CHUNK/4/NT)         // 64 float4 per thread
#define NEGINF (-3.402823466e+38f)

// Scratch (device globals; no allocations allowed)
__device__ float g_psum[NBLK];
__device__ float g_fk [NBLK]; __device__ int g_fi [NBLK];
__device__ float g_b1u[NBLK]; __device__ int g_b1i[NBLK]; __device__ float g_b1c[NBLK];
__device__ float g_b2u[NBLK]; __device__ int g_b2i[NBLK]; __device__ float g_b2c[NBLK];
__device__ unsigned int g_ctr;   // zero-init; last block resets each launch

__device__ __forceinline__ bool better(float s, int i, float s2, int i2) {
    return s > s2 || (s == s2 && i < i2);
}

// -ln(u): poly in t=1-u where argmax contenders live (rel err < 1e-8 for
// t < 1/16), MUFU lg2 elsewhere (non-contenders; their error is harmless).
__device__ __forceinline__ float neg_ln(float u) {
    u = fmaxf(u, 1e-12f);            // reference clip (upper clip no-op in fp32)
    float t = 1.0f - u;
    float wp = t*(1.0f + t*(0.5f + t*(0.33333334f + t*(0.25f +
               t*(0.2f + t*(0.16666667f + t*0.14285715f))))));
    float wm = __log2f(u) * -0.69314718f;
    return (t < 0.0625f) ? wp : wm;
}

__global__ void __launch_bounds__(NT, 2)
k_all(const float* __restrict__ x, const float* __restrict__ ufg,
      const float* __restrict__ ubg, float* __restrict__ out) {
    int blk = blockIdx.x;
    int b = blk / SPLIT, ch = blk % SPLIT;
    size_t off = (size_t)b*HW + (size_t)ch*CHUNK;
    const float4* cam = reinterpret_cast<const float4*>(x + off);
    const float4* uf  = reinterpret_cast<const float4*>(ufg + off);
    const float4* ub  = reinterpret_cast<const float4*>(ubg + off);
    float4* op = reinterpret_cast<float4*>(out + off);
    int t = threadIdx.x;

    float sum = 0.f;
    float fk = NEGINF; int fi = 0;
    float bu = -1.f;   int bi = 0; float bc = 0.f;
    const float4 fill = make_float4(-255.f, -255.f, -255.f, -255.f);

    // software pipeline: prefetch next iteration's 3 float4s while computing
    float4 c = cam[t];
    float4 f = uf[t];
    float4 g = ub[t];

    #pragma unroll 8
    for (int it = 0; it < NV; ++it) {
        float4 cn, fn, gn;
        if (it + 1 < NV) {
            int vn = (it+1)*NT + t;
            cn = cam[vn]; fn = uf[vn]; gn = ub[vn];
        }
        op[it*NT + t] = fill;
        int base = ch*CHUNK + (it*NT + t)*4;
        float cc[4] = {c.x, c.y, c.z, c.w};
        float ff[4] = {f.x, f.y, f.z, f.w};
        float gg[4] = {g.x, g.y, g.z, g.w};
        #pragma unroll
        for (int j = 0; j < 4; ++j) {
            float ce = cc[j] + 1e-6f;
            sum += ce;
            float key = __fdividef(ce, neg_ln(ff[j]));   // fg rank key
            if (key > fk) { fk = key; fi = base + j; }   // ascending idx -> strict >
            float u = gg[j];
            if (u > bu) { bu = u; bi = base + j; bc = cc[j]; }
        }
        if (it + 1 < NV) { c = cn; f = fn; g = gn; }
    }

    __shared__ float s_sum[NT];
    __shared__ float s_fk[NT];  __shared__ int s_fi[NT];
    __shared__ float s_b1u[NT]; __shared__ int s_b1i[NT]; __shared__ float s_b1c[NT];
    __shared__ float s_b2u[NT]; __shared__ int s_b2i[NT]; __shared__ float s_b2c[NT];
    s_sum[t] = sum;
    s_fk[t] = fk;  s_fi[t] = fi;
    s_b1u[t] = bu; s_b1i[t] = bi; s_b1c[t] = bc;
    s_b2u[t] = -1.f; s_b2i[t] = 0x7FFFFFFF; s_b2c[t] = 0.f;
    __syncthreads();

    for (int o = NT/2; o > 0; o >>= 1) {
        if (t < o) {
            s_sum[t] += s_sum[t + o];
            if (better(s_fk[t+o], s_fi[t+o], s_fk[t], s_fi[t])) {
                s_fk[t] = s_fk[t+o]; s_fi[t] = s_fi[t+o];
            }
            float a1 = s_b1u[t],   b1 = s_b1u[t+o];
            int   a1i = s_b1i[t],  b1i = s_b1i[t+o];
            float a1c = s_b1c[t],  b1c = s_b1c[t+o];
            float a2 = s_b2u[t],   b2 = s_b2u[t+o];
            int   a2i = s_b2i[t],  b2i = s_b2i[t+o];
            float a2c = s_b2c[t],  b2c = s_b2c[t+o];
            if (better(b1, b1i, a1, a1i)) {
                s_b1u[t] = b1; s_b1i[t] = b1i; s_b1c[t] = b1c;
                if (better(a1, a1i, b2, b2i)) { s_b2u[t] = a1; s_b2i[t] = a1i; s_b2c[t] = a1c; }
                else                          { s_b2u[t] = b2; s_b2i[t] = b2i; s_b2c[t] = b2c; }
            } else {
                if (better(b1, b1i, a2, a2i)) { s_b2u[t] = b1; s_b2i[t] = b1i; s_b2c[t] = b1c; }
            }
        }
        __syncthreads();
    }
    __shared__ bool is_last;
    if (t == 0) {
        g_psum[blk] = s_sum[0];
        g_fk[blk] = s_fk[0];   g_fi[blk] = s_fi[0];
        g_b1u[blk] = s_b1u[0]; g_b1i[blk] = s_b1i[0]; g_b1c[blk] = s_b1c[0];
        g_b2u[blk] = s_b2u[0]; g_b2i[blk] = s_b2i[0]; g_b2c[blk] = s_b2c[0];
        __threadfence();                           // publish partials + fill stores
        unsigned int v = atomicAdd(&g_ctr, 1u);
        is_last = (v == (unsigned)(NBLK - 1));
    }
    __syncthreads();
    if (!is_last) return;

    // ---- last block: finalize all batches (one thread per batch) ----
    if (t == 0) g_ctr = 0;                         // reset for next graph replay
    if (t >= BATCH) return;
    int bb = t;

    float S = 0.f;
    #pragma unroll
    for (int c2 = 0; c2 < SPLIT; ++c2) S += g_psum[bb*SPLIT + c2];
    float invS = 1.0f / S;

    float ffk = NEGINF; int ffi = 0;
    #pragma unroll
    for (int c2 = 0; c2 < SPLIT; ++c2) {
        float s = g_fk[bb*SPLIT + c2]; int i = g_fi[bb*SPLIT + c2];
        if (better(s, i, ffk, ffi)) { ffk = s; ffi = i; }
    }

    // bg: exact reference scoring of the 4 candidates
    float bsc = NEGINF; int bbi = 0;
    #pragma unroll
    for (int c2 = 0; c2 < SPLIT; ++c2) {
        int k = bb*SPLIT + c2;
        #pragma unroll
        for (int w = 0; w < 2; ++w) {
            float u   = w ? g_b2u[k] : g_b1u[k];
            int   idx = w ? g_b2i[k] : g_b1i[k];
            float cm  = w ? g_b2c[k] : g_b1c[k];
            float uc = fmaxf(u, 1e-12f);
            float gmb = -logf(-logf(uc));
            float p = (cm + 1e-6f) * invS;
            float s = log1pf(-p) + gmb;
            if (better(s, idx, bsc, bbi)) { bsc = s; bbi = idx; }
        }
    }

    int fr = ffi >> 9, fc = ffi & 511;
    int br = bbi >> 9, bc2 = bbi & 511;
    float* o = out + (size_t)bb*HW;
    #pragma unroll
    for (int dr = -1; dr <= 1; ++dr) {
        #pragma unroll
        for (int dc = -1; dc <= 1; ++dc) {
            int r = fr + dr, c2 = fc + dc;
            if (r >= 0 && r < HDIM && c2 >= 0 && c2 < WDIM &&
                !(abs(r - br) <= 1 && abs(c2 - bc2) <= 1))
                o[r*WDIM + c2] = 1.0f;
            r = br + dr; c2 = bc2 + dc;
            if (r >= 0 && r < HDIM && c2 >= 0 && c2 < WDIM &&
                !(abs(r - fr) <= 1 && abs(c2 - fc) <= 1))
                o[r*WDIM + c2] = 0.0f;
        }
    }
}

extern "C" void kernel_launch(void* const* d_in, const int* in_sizes, int n_in,
                              void* d_out, int out_size) {
    const float* x   = (const float*)d_in[0];
    const float* ufg = (const float*)d_in[1];
    const float* ubg = (const float*)d_in[2];
    float* out = (float*)d_out;
    k_all<<<NBLK, NT>>>(x, ufg, ubg, out);
}